// round 8
// baseline (speedup 1.0000x reference)
#include <cuda_runtime.h>
#include <cuda_bf16.h>

#define NB 4096
#define FULLMASK 0xFFFFFFFFu

// ---------------- device-global state (no allocations allowed) ----------------
__device__ unsigned int       g_cnt[NB];   // per-bin counts
__device__ unsigned long long g_msum[NB];  // per-bin sum of low-20-mantissa-bits

// ---------------- K0: zero state ----------------
__global__ void k_zero() {
    int i = blockIdx.x * blockDim.x + threadIdx.x;
    if (i < NB) { g_cnt[i] = 0u; g_msum[i] = 0ull; }
}

// fast relative error: ~2-3 ulp from __fdividef; self-consistent (same value binned and summed)
__device__ __forceinline__ float rel_err(float o, float t) {
    float r = __fdividef(t - o, t);
    return r * r;
}

// ---------------- K1: fused histogram + exact per-bin sums, ONE pass ----------------
// key = float bits of err (always >= 0). bin = key>>20 (sign+exp+3 mantissa bits).
// m = key & 0xFFFFF. err == v_lo(bin) + 2^exp(bin) * m * 2^-23 EXACTLY.
// One 64-bit shared atomic per element: (count in bits 48..63) | (sum of m in bits 0..47).
// Worst case per block: 56.7k elements all in one bin -> count < 2^16 OK, sum_m < 56.7k*2^20 < 2^48 OK.
__global__ __launch_bounds__(1024, 2) void k_fused(const float* __restrict__ out,
                                                   const float* __restrict__ tgt,
                                                   int n) {
    __shared__ unsigned long long sh[NB];   // 32 KB
    for (int i = threadIdx.x; i < NB; i += blockDim.x) sh[i] = 0ull;
    __syncthreads();

    int n4 = n >> 2;
    const float4* __restrict__ o4 = (const float4*)out;
    const float4* __restrict__ t4 = (const float4*)tgt;
    int stride = gridDim.x * blockDim.x;
    int i = blockIdx.x * blockDim.x + threadIdx.x;

    for (; i + stride < n4; i += 2 * stride) {
        float4 oa = o4[i];
        float4 ta = t4[i];
        float4 ob = o4[i + stride];
        float4 tb = t4[i + stride];
        unsigned int key[8];
        key[0] = __float_as_uint(rel_err(oa.x, ta.x));
        key[1] = __float_as_uint(rel_err(oa.y, ta.y));
        key[2] = __float_as_uint(rel_err(oa.z, ta.z));
        key[3] = __float_as_uint(rel_err(oa.w, ta.w));
        key[4] = __float_as_uint(rel_err(ob.x, tb.x));
        key[5] = __float_as_uint(rel_err(ob.y, tb.y));
        key[6] = __float_as_uint(rel_err(ob.z, tb.z));
        key[7] = __float_as_uint(rel_err(ob.w, tb.w));
#pragma unroll
        for (int j = 0; j < 8; j++) {
            unsigned long long add = (1ull << 48) | (unsigned long long)(key[j] & 0xFFFFFu);
            atomicAdd(&sh[key[j] >> 20], add);
        }
    }
    for (; i < n4; i += stride) {
        float4 o = o4[i];
        float4 t = t4[i];
        unsigned int key[4];
        key[0] = __float_as_uint(rel_err(o.x, t.x));
        key[1] = __float_as_uint(rel_err(o.y, t.y));
        key[2] = __float_as_uint(rel_err(o.z, t.z));
        key[3] = __float_as_uint(rel_err(o.w, t.w));
#pragma unroll
        for (int j = 0; j < 4; j++) {
            unsigned long long add = (1ull << 48) | (unsigned long long)(key[j] & 0xFFFFFu);
            atomicAdd(&sh[key[j] >> 20], add);
        }
    }
    // tail (n not multiple of 4)
    int tail_base = n4 << 2;
    int gtid = blockIdx.x * blockDim.x + threadIdx.x;
    if (tail_base + gtid < n) {
        unsigned int key = __float_as_uint(rel_err(out[tail_base + gtid], tgt[tail_base + gtid]));
        atomicAdd(&sh[key >> 20], (1ull << 48) | (unsigned long long)(key & 0xFFFFFu));
    }
    __syncthreads();

    // flush: unpack into separate global arrays (count overflow-safe globally)
    for (int b = threadIdx.x; b < NB; b += blockDim.x) {
        unsigned long long v = sh[b];
        if (v) {
            atomicAdd(&g_cnt[b], (unsigned int)(v >> 48));
            atomicAdd(&g_msum[b], v & 0xFFFFFFFFFFFFull);
        }
    }
}

// ---------------- K2: select bin + assemble result (single block) ----------------
__global__ __launch_bounds__(1024) void k_final(int n, float* __restrict__ result) {
    __shared__ unsigned long long s_warp[32];
    __shared__ double wsum[32];
    __shared__ unsigned int sB;
    __shared__ unsigned long long sBelow;

    int t = threadIdx.x;          // 0..1023
    int lane = t & 31;
    int wid = t >> 5;
    long long k = (long long)((double)n * 0.97);   // matches python int(N*0.97)

    // ---- parallel selection over 4096 counts, 4 bins/thread ----
    uint4 v = ((const uint4*)g_cnt)[t];
    unsigned int raw[4] = {v.x, v.y, v.z, v.w};
    unsigned long long thread_tot =
        (unsigned long long)raw[0] + raw[1] + raw[2] + raw[3];

    unsigned long long s = thread_tot;
#pragma unroll
    for (int off = 1; off < 32; off <<= 1) {
        unsigned long long u = __shfl_up_sync(FULLMASK, s, off);
        if (lane >= off) s += u;
    }
    if (lane == 31) s_warp[wid] = s;
    __syncthreads();
    if (wid == 0) {
        unsigned long long w = s_warp[lane];
        unsigned long long ws = w;
#pragma unroll
        for (int off = 1; off < 32; off <<= 1) {
            unsigned long long u = __shfl_up_sync(FULLMASK, ws, off);
            if (lane >= off) ws += u;
        }
        s_warp[lane] = ws - w;    // exclusive prefix of warp sums
    }
    __syncthreads();
    unsigned long long base = s_warp[wid] + (s - thread_tot);

    unsigned long long run = base;
#pragma unroll
    for (int j = 0; j < 4; j++) {
        unsigned long long exc = run;
        run += raw[j];
        if ((long long)exc < k && (long long)run >= k) {
            sB = (unsigned int)(t * 4 + j);
            sBelow = exc;
        }
    }
    __syncthreads();

    unsigned int B = sB;
    long long cbelow = (long long)sBelow;

    // ---- exact sum over bins strictly below B ----
    // bin b: v_lo = float(b<<20); pow2 = float((b>>3)<<23) (2^exp; 0 for denormal bin -> term ~0, fine)
    // bin_sum = cnt*v_lo + pow2 * msum * 2^-23   (exact)
    double part = 0.0;
    for (int b = t; b < (int)B; b += blockDim.x) {
        unsigned int c = g_cnt[b];
        if (c) {
            double vlo = (double)__uint_as_float(b << 20);
            double p2  = (double)__uint_as_float((unsigned int)(b >> 3) << 23);
            part += (double)c * vlo + p2 * (double)g_msum[b] * (1.0 / 8388608.0);
        }
    }
#pragma unroll
    for (int off = 16; off >= 1; off >>= 1)
        part += __shfl_down_sync(FULLMASK, part, off);
    if (lane == 0) wsum[wid] = part;
    __syncthreads();

    if (t == 0) {
        double sum_below = 0.0;
        for (int w = 0; w < 32; w++) sum_below += wsum[w];

        // boundary bin: take r smallest of its c elements.
        // calibrated interpolation: partial_msum ~= msum * (r/c)^2
        // (exact for uniform within-bin distribution; exact at r==c)
        long long r = k - cbelow;                 // 1..c
        unsigned int c = g_cnt[B];
        unsigned long long Sm = g_msum[B];
        double vlo = (double)__uint_as_float(B << 20);
        double p2  = (double)__uint_as_float((unsigned int)(B >> 3) << 23);
        double frac = (double)r / (double)c;
        double partial = (double)r * vlo + p2 * (double)Sm * frac * frac * (1.0 / 8388608.0);

        result[0] = (float)((sum_below + partial) / (double)k);
    }
}

// ---------------- launch ----------------
extern "C" void kernel_launch(void* const* d_in, const int* in_sizes, int n_in,
                              void* d_out, int out_size) {
    const float* output = (const float*)d_in[0];
    const float* target = (const float*)d_in[1];
    int n = in_sizes[0];
    if (n <= 0) return;

    k_zero<<<16, 256>>>();
    k_fused<<<296, 1024>>>(output, target, n);
    k_final<<<1, 1024>>>(n, (float*)d_out);
}